// round 17
// baseline (speedup 1.0000x reference)
#include <cuda_runtime.h>
#include <cstdint>

#define BB 16
#define TT 512
#define DD 384
#define OUT_LEN 3584            // T * (MAX_DUR - 1)
#define ROW_BYTES (DD * 4)      // 1536
#define ROWS 16                 // output rows per block (2 per warp)
#define BLOCKS_PER_B (OUT_LEN / ROWS)   // 224
#define NT 256
#define V4 (DD / 4)             // 96 float4 per row
#define ZR 4                    // zero-buffer rows (6 KB)

// R15 + split store paths: valid rows via LSU (__stcs), pad rows via TMA
// bulk stores from a zeroed smem buffer (async engine, off the L1 path).
__global__ void __launch_bounds__(NT, 8)
lr_fused(const float* __restrict__ xs, const int* __restrict__ ds,
         const int* __restrict__ ilens, float* __restrict__ out) {
    __shared__ int csum[TT];
    __shared__ int wtot[8];
    __shared__ int srcs[ROWS];
    __shared__ alignas(128) float4 zbuf[ZR * V4];   // 6144 B of zeros

    const int tid = threadIdx.x;
    const int lane = tid & 31;
    const int w = tid >> 5;               // 8 warps
    const int b = blockIdx.y;
    const int r0 = blockIdx.x * ROWS;

    // ---- zero the pad buffer (384 float4 over 256 threads) ----
    const float4 zero = make_float4(0.f, 0.f, 0.f, 0.f);
    zbuf[tid] = zero;
    if (tid < ZR * V4 - NT) zbuf[NT + tid] = zero;

    // ---- masked duration load: 2 consecutive per thread ----
    const int ilen = __ldg(ilens + b);
    int2 dv = ((const int2*)(ds + b * TT))[tid];
    const int g0 = tid * 2;
    int d0 = (g0 + 0 < ilen) ? dv.x : 0;
    int d1 = (g0 + 1 < ilen) ? dv.y : 0;
    int p1 = d0 + d1;

    // ---- block inclusive scan -> csum ----
    int x = p1;
    #pragma unroll
    for (int off = 1; off < 32; off <<= 1) {
        int y = __shfl_up_sync(0xFFFFFFFFu, x, off);
        if (lane >= off) x += y;
    }
    if (lane == 31) wtot[w] = x;
    __syncthreads();
    int woff = 0;
    #pragma unroll
    for (int i = 0; i < 8; ++i) woff += (i < w) ? wtot[i] : 0;
    const int excl = woff + x - p1;
    csum[g0 + 0] = excl + d0;
    csum[g0 + 1] = excl + p1;
    __syncthreads();                       // csum + zbuf ready

    const int total = csum[TT - 1];
    const int p = min(max(total - r0, 0), ROWS);   // valid rows are a prefix

    // ---- pad rows [p, ROWS): TMA bulk stores of zeros (async engine) ----
    const bool has_pad = (p < ROWS);
    if (tid == 0 && has_pad) {
        uint32_t zb_s = (uint32_t)__cvta_generic_to_shared(zbuf);
        asm volatile("fence.proxy.async.shared::cta;" ::: "memory");
        #pragma unroll
        for (int k = 0; k < ROWS / ZR; ++k) {      // 4 chunks max
            const int rs = p + k * ZR;
            if (rs < ROWS) {
                const int nr = min(ZR, ROWS - rs);
                char* dst = (char*)(out + ((size_t)b * OUT_LEN + r0 + rs) * DD);
                asm volatile(
                    "cp.async.bulk.global.shared::cta.bulk_group [%0], [%1], %2;"
                    :: "l"(dst), "r"(zb_s), "r"((uint32_t)(nr * ROW_BYTES))
                    : "memory");
            }
        }
        asm volatile("cp.async.bulk.commit_group;" ::: "memory");
    }

    // ---- searchsorted(csum, t, 'right') for valid rows ----
    if (tid < ROWS) {
        int s = -1;
        if (tid < p) {
            const int t = r0 + tid;
            int lo = 0, hi = TT;
            #pragma unroll
            for (int it = 0; it < 10; ++it) {
                int mid = (lo + hi) >> 1;
                if (csum[mid] <= t) lo = mid + 1; else hi = mid;
            }
            s = lo;
        }
        srcs[tid] = s;
    }
    __syncthreads();

    // ---- warp-per-row gather (valid rows only): warp w -> rows 2w, 2w+1 ----
    const float4* __restrict__ xb = (const float4*)xs + (size_t)b * TT * V4;
    float4* __restrict__ ob = (float4*)out + ((size_t)b * OUT_LEN + r0) * V4;

    const int ra = 2 * w;
    const int rb = ra + 1;
    const int sa = srcs[ra];              // broadcast LDS
    const int sb = srcs[rb];

    if (sa >= 0) {
        const float4* sra = xb + sa * V4 + lane;
        float4 va0 = sra[0], va1 = sra[32], va2 = sra[64];
        float4* da = ob + ra * V4 + lane;
        __stcs(da, va0); __stcs(da + 32, va1); __stcs(da + 64, va2);
    }
    if (sb >= 0) {
        const float4* srb = xb + sb * V4 + lane;
        float4 vb0 = srb[0], vb1 = srb[32], vb2 = srb[64];
        float4* db = ob + rb * V4 + lane;
        __stcs(db, vb0); __stcs(db + 32, vb1); __stcs(db + 64, vb2);
    }

    // ---- drain TMA smem reads before CTA exit ----
    if (tid == 0 && has_pad) {
        asm volatile("cp.async.bulk.wait_group.read 0;" ::: "memory");
    }
}

extern "C" void kernel_launch(void* const* d_in, const int* in_sizes, int n_in,
                              void* d_out, int out_size) {
    const float* xs = (const float*)d_in[0];
    const int* ds = (const int*)d_in[1];
    const int* ilens = (const int*)d_in[2];
    float* out = (float*)d_out;

    dim3 grid(BLOCKS_PER_B, BB);    // (224, 16) = 3584 blocks
    lr_fused<<<grid, NT>>>(xs, ds, ilens, out);
}